// round 8
// baseline (speedup 1.0000x reference)
#include <cuda_runtime.h>
#include <cuda_bf16.h>
#include <math.h>

// Problem constants
#define BATCH 8
#define CH    512
#define T     1024
#define HEADS 8
#define GROUPS 32
#define HCH   64          // channels per head
#define EPS   1e-5f

// Scratch (allocation-free rule: __device__ globals)
__device__ float g_xn  [BATCH * CH * T];        // 16 MB  normalized input
__device__ float g_qkv [BATCH * 3 * CH * T];    // 48 MB  qkv projections
__device__ float g_attn[BATCH * CH * T];        // 16 MB  attention output

// ---------------------------------------------------------------------------
// GroupNorm: one block per (b, group). group = 16 channels x 1024 t = 16384
// ---------------------------------------------------------------------------
__global__ __launch_bounds__(256) void groupnorm_kernel(
    const float* __restrict__ x, const float* __restrict__ w,
    const float* __restrict__ b, float* __restrict__ out)
{
    const int blk = blockIdx.x;            // b*32 + g
    const int bb = blk >> 5, g = blk & 31;
    const float* xp = x + ((size_t)bb * CH + g * 16) * T;
    float* op = out + ((size_t)bb * CH + g * 16) * T;

    float s = 0.f, s2 = 0.f;
    for (int i = threadIdx.x; i < 16 * T; i += 256) {
        float v = xp[i];
        s += v; s2 += v * v;
    }
    __shared__ float rs[256], rq[256];
    rs[threadIdx.x] = s; rq[threadIdx.x] = s2;
    __syncthreads();
    for (int off = 128; off > 0; off >>= 1) {
        if (threadIdx.x < off) {
            rs[threadIdx.x] += rs[threadIdx.x + off];
            rq[threadIdx.x] += rq[threadIdx.x + off];
        }
        __syncthreads();
    }
    const float inv_n = 1.0f / (16.0f * T);
    const float mu  = rs[0] * inv_n;
    const float var = rq[0] * inv_n - mu * mu;
    const float rinv = rsqrtf(var + EPS);

    for (int i = threadIdx.x; i < 16 * T; i += 256) {
        int cl = i >> 10;                 // local channel 0..15
        int c = g * 16 + cl;
        float v = xp[i];
        op[i] = (v - mu) * rinv * w[c] + b[c];
    }
}

// ---------------------------------------------------------------------------
// Batched GEMM: out[b,o,t] = sum_c W[o,c] * X[b,c,t] + bias[o] (+ residual)
// BM=BN=128, BK=8, 256 threads, 8x8 micro-tile. Double-buffered smem.
// K is a compile-time constant (512 for both calls).
// ---------------------------------------------------------------------------
template <int K>
__global__ __launch_bounds__(256) void gemm_kernel(
    const float* __restrict__ W, const float* __restrict__ X,
    const float* __restrict__ bias, const float* __restrict__ res,
    float* __restrict__ out, int O, int Tn)
{
    __shared__ float Ws[2][8][132];
    __shared__ float Xs[2][8][132];

    const int tid = threadIdx.x;
    const int tx = tid & 15, ty = tid >> 4;
    const size_t batch_off = (size_t)blockIdx.z * K * Tn;
    const size_t obatch_off = (size_t)blockIdx.z * O * Tn;
    const float* Xb = X + batch_off;
    float* outb = out + obatch_off;
    const float* resb = res ? res + obatch_off : nullptr;

    const int row0 = blockIdx.y * 128;
    const int col0 = blockIdx.x * 128;

    const int wm  = tid >> 1;             // 0..127
    const int wk4 = (tid & 1) * 4;        // 0 or 4
    const int xk  = tid >> 5;             // 0..7
    const int xn4 = (tid & 31) * 4;       // 0..124

    float acc[8][8];
#pragma unroll
    for (int i = 0; i < 8; i++)
#pragma unroll
        for (int j = 0; j < 8; j++) acc[i][j] = 0.f;

    // Preload tile kt=0 into buffer 0
    {
        float4 wv = *(const float4*)&W[(size_t)(row0 + wm) * K + wk4];
        Ws[0][wk4 + 0][wm] = wv.x;
        Ws[0][wk4 + 1][wm] = wv.y;
        Ws[0][wk4 + 2][wm] = wv.z;
        Ws[0][wk4 + 3][wm] = wv.w;
        *(float4*)&Xs[0][xk][xn4] =
            *(const float4*)&Xb[(size_t)xk * Tn + col0 + xn4];
    }
    __syncthreads();

    int buf = 0;
    for (int kt = 0; kt < K; kt += 8) {
        const int nkt = kt + 8;
        const bool more = nkt < K;
        float4 wn, xv;
        if (more) {
            wn = *(const float4*)&W[(size_t)(row0 + wm) * K + nkt + wk4];
            xv = *(const float4*)&Xb[(size_t)(nkt + xk) * Tn + col0 + xn4];
        }
#pragma unroll
        for (int k = 0; k < 8; k++) {
            float a[8], bv[8];
            *(float4*)&a[0]  = *(const float4*)&Ws[buf][k][ty * 8];
            *(float4*)&a[4]  = *(const float4*)&Ws[buf][k][ty * 8 + 4];
            *(float4*)&bv[0] = *(const float4*)&Xs[buf][k][tx * 8];
            *(float4*)&bv[4] = *(const float4*)&Xs[buf][k][tx * 8 + 4];
#pragma unroll
            for (int i = 0; i < 8; i++)
#pragma unroll
                for (int j = 0; j < 8; j++)
                    acc[i][j] = fmaf(a[i], bv[j], acc[i][j]);
        }
        if (more) {
            const int nb = buf ^ 1;
            Ws[nb][wk4 + 0][wm] = wn.x;
            Ws[nb][wk4 + 1][wm] = wn.y;
            Ws[nb][wk4 + 2][wm] = wn.z;
            Ws[nb][wk4 + 3][wm] = wn.w;
            *(float4*)&Xs[nb][xk][xn4] = xv;
            __syncthreads();
            buf = nb;
        }
    }

#pragma unroll
    for (int i = 0; i < 8; i++) {
        const int o = row0 + ty * 8 + i;
        const float bo = bias[o];
        const size_t rowbase = (size_t)o * Tn + col0 + tx * 8;
#pragma unroll
        for (int j4 = 0; j4 < 8; j4 += 4) {
            float4 v;
            v.x = acc[i][j4 + 0] + bo;
            v.y = acc[i][j4 + 1] + bo;
            v.z = acc[i][j4 + 2] + bo;
            v.w = acc[i][j4 + 3] + bo;
            if (resb) {
                float4 r = *(const float4*)&resb[rowbase + j4];
                v.x += r.x; v.y += r.y; v.z += r.z; v.w += r.w;
            }
            *(float4*)&outb[rowbase + j4] = v;
        }
    }
}

// ---------------------------------------------------------------------------
// Fused flash attention. One block per (bh, q-tile of 64). BS=32 key tiles.
// qkv layout per batch: row (h*192 + c) for q, +64 for k, +128 for v.
// Softmax parallelized: 4 threads per row (row = tid>>2, sub = tid&3),
// shuffle all-reduce within the aligned 4-lane group.
// ---------------------------------------------------------------------------
__global__ __launch_bounds__(256) void attn_kernel(
    const float* __restrict__ qkv, float* __restrict__ aout)
{
    const int bh = blockIdx.x;            // 0..63
    const int qt = blockIdx.y;            // 0..15
    const int bb = bh >> 3, h = bh & 7;
    const float* base = qkv + (size_t)bb * 3 * CH * T;
    const float* qp = base + (size_t)(h * 192) * T;
    const float* kp = base + (size_t)(h * 192 + 64) * T;
    const float* vp = base + (size_t)(h * 192 + 128) * T;

    __shared__ float Qs[64][64];   // [c][q]
    __shared__ float Ks[64][33];   // [c][s]
    __shared__ float Vs[64][33];   // [c][s]
    __shared__ float Sm[64][33];   // [q][s]
    __shared__ float lsc[64];      // per-row rescale factor
    __shared__ float linv[64];     // final 1/l

    const int tid = threadIdx.x;
    const int tx = tid & 15, ty = tid >> 4;
    const int srow = tid >> 2;            // softmax row 0..63
    const int ssub = tid & 3;             // 8 s-values each

    for (int e = tid; e < 64 * 64; e += 256) {
        int c = e >> 6, q = e & 63;
        Qs[c][q] = qp[(size_t)c * T + qt * 64 + q];
    }

    float m_r = -1e30f, l_r = 0.f;   // replicated across the 4 sub-threads
    float acc[4][4];
#pragma unroll
    for (int i = 0; i < 4; i++)
#pragma unroll
        for (int j = 0; j < 4; j++) acc[i][j] = 0.f;

    __syncthreads();

    for (int st = 0; st < 32; st++) {
        for (int e = tid; e < 64 * 32; e += 256) {
            int c = e >> 5, s = e & 31;
            Ks[c][s] = kp[(size_t)c * T + st * 32 + s];
            Vs[c][s] = vp[(size_t)c * T + st * 32 + s];
        }
        __syncthreads();

        // scores: thread covers q = ty*4+i (4), s = tx*2+j (2)
        {
            float sc[4][2];
#pragma unroll
            for (int i = 0; i < 4; i++) { sc[i][0] = 0.f; sc[i][1] = 0.f; }
#pragma unroll
            for (int c = 0; c < 64; c++) {
                float4 qv = *(const float4*)&Qs[c][ty * 4];
                float k0 = Ks[c][tx * 2];
                float k1 = Ks[c][tx * 2 + 1];
                sc[0][0] = fmaf(qv.x, k0, sc[0][0]);
                sc[0][1] = fmaf(qv.x, k1, sc[0][1]);
                sc[1][0] = fmaf(qv.y, k0, sc[1][0]);
                sc[1][1] = fmaf(qv.y, k1, sc[1][1]);
                sc[2][0] = fmaf(qv.z, k0, sc[2][0]);
                sc[2][1] = fmaf(qv.z, k1, sc[2][1]);
                sc[3][0] = fmaf(qv.w, k0, sc[3][0]);
                sc[3][1] = fmaf(qv.w, k1, sc[3][1]);
            }
#pragma unroll
            for (int i = 0; i < 4; i++) {
                Sm[ty * 4 + i][tx * 2 + 0] = sc[i][0] * 0.125f;  // 64^-0.5
                Sm[ty * 4 + i][tx * 2 + 1] = sc[i][1] * 0.125f;
            }
        }
        __syncthreads();

        // online softmax: 4 threads per row, 8 s-values each.
        // sub-threads are lanes 4r..4r+3 of one warp -> xor-shuffle all-reduce.
        {
            const int s0 = ssub * 8;
            float mx = m_r;
#pragma unroll
            for (int s = 0; s < 8; s++) mx = fmaxf(mx, Sm[srow][s0 + s]);
            mx = fmaxf(mx, __shfl_xor_sync(0xffffffffu, mx, 1));
            mx = fmaxf(mx, __shfl_xor_sync(0xffffffffu, mx, 2));
            float fac = __expf(m_r - mx);
            float sum = 0.f;
#pragma unroll
            for (int s = 0; s < 8; s++) {
                float p = __expf(Sm[srow][s0 + s] - mx);
                Sm[srow][s0 + s] = p;
                sum += p;
            }
            sum += __shfl_xor_sync(0xffffffffu, sum, 1);
            sum += __shfl_xor_sync(0xffffffffu, sum, 2);
            l_r = l_r * fac + sum;
            m_r = mx;
            if (ssub == 0) lsc[srow] = fac;
        }
        __syncthreads();

        // rescale and accumulate O[q][c] += P[q][s] V[c][s]
        {
            float f[4];
#pragma unroll
            for (int i = 0; i < 4; i++) f[i] = lsc[ty * 4 + i];
#pragma unroll
            for (int i = 0; i < 4; i++)
#pragma unroll
                for (int j = 0; j < 4; j++) acc[i][j] *= f[i];
#pragma unroll 4
            for (int s = 0; s < 32; s++) {
                float p[4], v[4];
#pragma unroll
                for (int i = 0; i < 4; i++) p[i] = Sm[ty * 4 + i][s];
#pragma unroll
                for (int j = 0; j < 4; j++) v[j] = Vs[tx * 4 + j][s];
#pragma unroll
                for (int i = 0; i < 4; i++)
#pragma unroll
                    for (int j = 0; j < 4; j++)
                        acc[i][j] = fmaf(p[i], v[j], acc[i][j]);
            }
        }
        __syncthreads();
    }

    if (ssub == 0) linv[srow] = 1.0f / l_r;
    __syncthreads();

    // a[b, h*64 + c, t]  (c = tx*4+j, t = qt*64 + ty*4+i)
#pragma unroll
    for (int j = 0; j < 4; j++) {
        const size_t rowbase = ((size_t)bb * CH + h * 64 + tx * 4 + j) * T
                               + qt * 64 + ty * 4;
#pragma unroll
        for (int i = 0; i < 4; i++) {
            aout[rowbase + i] = acc[i][j] * linv[ty * 4 + i];
        }
    }
}

// ---------------------------------------------------------------------------
extern "C" void kernel_launch(void* const* d_in, const int* in_sizes, int n_in,
                              void* d_out, int out_size)
{
    const float* x      = (const float*)d_in[0];
    const float* norm_w = (const float*)d_in[1];
    const float* norm_b = (const float*)d_in[2];
    const float* qkv_w  = (const float*)d_in[3];
    const float* qkv_b  = (const float*)d_in[4];
    const float* proj_w = (const float*)d_in[5];
    const float* proj_b = (const float*)d_in[6];
    float* out = (float*)d_out;

    float* xn;   cudaGetSymbolAddress((void**)&xn,   g_xn);
    float* qkv;  cudaGetSymbolAddress((void**)&qkv,  g_qkv);
    float* attn; cudaGetSymbolAddress((void**)&attn, g_attn);

    // 1. GroupNorm
    groupnorm_kernel<<<BATCH * GROUPS, 256>>>(x, norm_w, norm_b, xn);

    // 2. QKV GEMM: (1536 x 512) x (512 x 1024) per batch
    gemm_kernel<CH><<<dim3(T / 128, (3 * CH) / 128, BATCH), 256>>>(
        qkv_w, xn, qkv_b, nullptr, qkv, 3 * CH, T);

    // 3. Fused attention
    attn_kernel<<<dim3(BATCH * HEADS, T / 64), 256>>>(qkv, attn);

    // 4. Proj GEMM + bias + residual
    gemm_kernel<CH><<<dim3(T / 128, CH / 128, BATCH), 256>>>(
        proj_w, attn, proj_b, x, out, CH, T);
}

// round 9
// speedup vs baseline: 1.3622x; 1.3622x over previous
#include <cuda_runtime.h>
#include <cuda_bf16.h>
#include <math.h>
#include <stdint.h>

// Problem constants
#define BATCH 8
#define CH    512
#define T     1024
#define HEADS 8
#define GROUPS 32
#define EPS   1e-5f

// Scratch (allocation-free rule: __device__ globals)
__device__ float g_xn  [BATCH * CH * T];        // 16 MB  normalized input
__device__ float g_qkv [BATCH * 3 * CH * T];    // 48 MB  qkv projections
__device__ float g_attn[BATCH * CH * T];        // 16 MB  attention output

// ---------------------------------------------------------------------------
// GroupNorm: one block per (b, group). group = 16 channels x 1024 t
// ---------------------------------------------------------------------------
__global__ __launch_bounds__(256) void groupnorm_kernel(
    const float* __restrict__ x, const float* __restrict__ w,
    const float* __restrict__ b, float* __restrict__ out)
{
    const int blk = blockIdx.x;            // b*32 + g
    const int bb = blk >> 5, g = blk & 31;
    const float* xp = x + ((size_t)bb * CH + g * 16) * T;
    float* op = out + ((size_t)bb * CH + g * 16) * T;

    float s = 0.f, s2 = 0.f;
    for (int i = threadIdx.x; i < 16 * T; i += 256) {
        float v = xp[i];
        s += v; s2 += v * v;
    }
    __shared__ float rs[256], rq[256];
    rs[threadIdx.x] = s; rq[threadIdx.x] = s2;
    __syncthreads();
    for (int off = 128; off > 0; off >>= 1) {
        if (threadIdx.x < off) {
            rs[threadIdx.x] += rs[threadIdx.x + off];
            rq[threadIdx.x] += rq[threadIdx.x + off];
        }
        __syncthreads();
    }
    const float inv_n = 1.0f / (16.0f * T);
    const float mu  = rs[0] * inv_n;
    const float var = rq[0] * inv_n - mu * mu;
    const float rinv = rsqrtf(var + EPS);

    for (int i = threadIdx.x; i < 16 * T; i += 256) {
        int cl = i >> 10;
        int c = g * 16 + cl;
        float v = xp[i];
        op[i] = (v - mu) * rinv * w[c] + b[c];
    }
}

// ---------------------------------------------------------------------------
// tf32 tensor-core GEMM: out[b,o,t] = sum_c W[o,c]*X[b,c,t] + bias[o] (+res)
// BM=128, BN=128, BK=16, 256 threads = 8 warps (2 m x 4 n),
// warp tile 64x32 = 4x4 m16n8k8 atoms. Double-buffered smem, tf32 via cvt.rna.
// ---------------------------------------------------------------------------
__device__ __forceinline__ uint32_t f2tf32(float f) {
    uint32_t u;
    asm("cvt.rna.tf32.f32 %0, %1;" : "=r"(u) : "f"(f));
    return u;
}

#define MMA_TF32(d, a, b)                                                   \
    asm volatile(                                                           \
        "mma.sync.aligned.m16n8k8.row.col.f32.tf32.tf32.f32 "               \
        "{%0,%1,%2,%3}, {%4,%5,%6,%7}, {%8,%9}, {%0,%1,%2,%3};"             \
        : "+f"(d[0]), "+f"(d[1]), "+f"(d[2]), "+f"(d[3])                    \
        : "r"(a[0]), "r"(a[1]), "r"(a[2]), "r"(a[3]), "r"(b[0]), "r"(b[1]))

template <int K>
__global__ __launch_bounds__(256) void gemm_tc_kernel(
    const float* __restrict__ W, const float* __restrict__ X,
    const float* __restrict__ bias, const float* __restrict__ res,
    float* __restrict__ out, int O, int Tn)
{
    // pads: A stride 20 -> (20*gid+tig)%32 all-distinct; B stride 136 -> (8k+n)%32 all-distinct
    __shared__ uint32_t As[2][128][20];
    __shared__ uint32_t Bs[2][16][136];

    const int tid  = threadIdx.x;
    const int lane = tid & 31;
    const int warp = tid >> 5;
    const int gid  = lane >> 2;     // 0..7
    const int tig  = lane & 3;      // 0..3
    const int m_warp = (warp & 1) * 64;
    const int n_warp = (warp >> 1) * 32;

    const int row0 = blockIdx.y * 128;
    const int col0 = blockIdx.x * 128;
    const float* Xb  = X + (size_t)blockIdx.z * K * Tn;
    float* outb      = out + (size_t)blockIdx.z * O * Tn;
    const float* resb = res ? res + (size_t)blockIdx.z * O * Tn : nullptr;

    // loader indices
    const int ar  = tid >> 2;           // 0..63  (A rows ar, ar+64)
    const int ac4 = (tid & 3) * 4;      // k offset within 16
    const int br  = tid >> 5;           // 0..7   (B k-rows br, br+8)
    const int bc4 = (tid & 31) * 4;     // n offset within 128

    float acc[4][4][4];
#pragma unroll
    for (int i = 0; i < 4; i++)
#pragma unroll
        for (int j = 0; j < 4; j++)
#pragma unroll
            for (int v = 0; v < 4; v++) acc[i][j][v] = 0.f;

    // preload tile kt=0
    {
        float4 w0 = *(const float4*)&W[(size_t)(row0 + ar) * K + ac4];
        float4 w1 = *(const float4*)&W[(size_t)(row0 + ar + 64) * K + ac4];
        float4 x0 = *(const float4*)&Xb[(size_t)br * Tn + col0 + bc4];
        float4 x1 = *(const float4*)&Xb[(size_t)(br + 8) * Tn + col0 + bc4];
        *(uint4*)&As[0][ar][ac4]      = make_uint4(f2tf32(w0.x), f2tf32(w0.y), f2tf32(w0.z), f2tf32(w0.w));
        *(uint4*)&As[0][ar + 64][ac4] = make_uint4(f2tf32(w1.x), f2tf32(w1.y), f2tf32(w1.z), f2tf32(w1.w));
        *(uint4*)&Bs[0][br][bc4]      = make_uint4(f2tf32(x0.x), f2tf32(x0.y), f2tf32(x0.z), f2tf32(x0.w));
        *(uint4*)&Bs[0][br + 8][bc4]  = make_uint4(f2tf32(x1.x), f2tf32(x1.y), f2tf32(x1.z), f2tf32(x1.w));
    }
    __syncthreads();

    int buf = 0;
    for (int kt = 0; kt < K; kt += 16) {
        const int nkt = kt + 16;
        const bool more = nkt < K;
        float4 w0, w1, x0, x1;
        if (more) {
            w0 = *(const float4*)&W[(size_t)(row0 + ar) * K + nkt + ac4];
            w1 = *(const float4*)&W[(size_t)(row0 + ar + 64) * K + nkt + ac4];
            x0 = *(const float4*)&Xb[(size_t)(nkt + br) * Tn + col0 + bc4];
            x1 = *(const float4*)&Xb[(size_t)(nkt + br + 8) * Tn + col0 + bc4];
        }

#pragma unroll
        for (int k8 = 0; k8 < 16; k8 += 8) {
            uint32_t bf[4][2];
#pragma unroll
            for (int na = 0; na < 4; na++) {
                bf[na][0] = Bs[buf][k8 + tig][n_warp + na * 8 + gid];
                bf[na][1] = Bs[buf][k8 + tig + 4][n_warp + na * 8 + gid];
            }
#pragma unroll
            for (int ma = 0; ma < 4; ma++) {
                uint32_t af[4];
                const int m0 = m_warp + ma * 16;
                af[0] = As[buf][m0 + gid][k8 + tig];
                af[1] = As[buf][m0 + gid + 8][k8 + tig];
                af[2] = As[buf][m0 + gid][k8 + tig + 4];
                af[3] = As[buf][m0 + gid + 8][k8 + tig + 4];
#pragma unroll
                for (int na = 0; na < 4; na++) {
                    MMA_TF32(acc[ma][na], af, bf[na]);
                }
            }
        }

        if (more) {
            const int nb = buf ^ 1;
            *(uint4*)&As[nb][ar][ac4]      = make_uint4(f2tf32(w0.x), f2tf32(w0.y), f2tf32(w0.z), f2tf32(w0.w));
            *(uint4*)&As[nb][ar + 64][ac4] = make_uint4(f2tf32(w1.x), f2tf32(w1.y), f2tf32(w1.z), f2tf32(w1.w));
            *(uint4*)&Bs[nb][br][bc4]      = make_uint4(f2tf32(x0.x), f2tf32(x0.y), f2tf32(x0.z), f2tf32(x0.w));
            *(uint4*)&Bs[nb][br + 8][bc4]  = make_uint4(f2tf32(x1.x), f2tf32(x1.y), f2tf32(x1.z), f2tf32(x1.w));
            __syncthreads();
            buf = nb;
        }
    }

    // epilogue: c0=(gid,2tig) c1=(gid,2tig+1) c2=(gid+8,2tig) c3=(gid+8,2tig+1)
#pragma unroll
    for (int ma = 0; ma < 4; ma++) {
        const int r0 = row0 + m_warp + ma * 16 + gid;
        const int r1 = r0 + 8;
        const float bo0 = bias[r0];
        const float bo1 = bias[r1];
#pragma unroll
        for (int na = 0; na < 4; na++) {
            const int n0 = col0 + n_warp + na * 8 + 2 * tig;
            float2 v0 = make_float2(acc[ma][na][0] + bo0, acc[ma][na][1] + bo0);
            float2 v1 = make_float2(acc[ma][na][2] + bo1, acc[ma][na][3] + bo1);
            if (resb) {
                float2 q0 = *(const float2*)&resb[(size_t)r0 * Tn + n0];
                float2 q1 = *(const float2*)&resb[(size_t)r1 * Tn + n0];
                v0.x += q0.x; v0.y += q0.y;
                v1.x += q1.x; v1.y += q1.y;
            }
            *(float2*)&outb[(size_t)r0 * Tn + n0] = v0;
            *(float2*)&outb[(size_t)r1 * Tn + n0] = v1;
        }
    }
}

// ---------------------------------------------------------------------------
// Fused flash attention (fp32). One block per (bh, q-tile of 64). BS=32.
// qkv layout per batch: row (h*192 + c) for q, +64 for k, +128 for v.
// ---------------------------------------------------------------------------
__global__ __launch_bounds__(256) void attn_kernel(
    const float* __restrict__ qkv, float* __restrict__ aout)
{
    const int bh = blockIdx.x;            // 0..63
    const int qt = blockIdx.y;            // 0..15
    const int bb = bh >> 3, h = bh & 7;
    const float* base = qkv + (size_t)bb * 3 * CH * T;
    const float* qp = base + (size_t)(h * 192) * T;
    const float* kp = base + (size_t)(h * 192 + 64) * T;
    const float* vp = base + (size_t)(h * 192 + 128) * T;

    __shared__ float Qs[64][64];
    __shared__ float Ks[64][33];
    __shared__ float Vs[64][33];
    __shared__ float Sm[64][33];
    __shared__ float lsc[64];
    __shared__ float linv[64];

    const int tid = threadIdx.x;
    const int tx = tid & 15, ty = tid >> 4;
    const int srow = tid >> 2;
    const int ssub = tid & 3;

    for (int e = tid; e < 64 * 64; e += 256) {
        int c = e >> 6, q = e & 63;
        Qs[c][q] = qp[(size_t)c * T + qt * 64 + q];
    }

    float m_r = -1e30f, l_r = 0.f;
    float acc[4][4];
#pragma unroll
    for (int i = 0; i < 4; i++)
#pragma unroll
        for (int j = 0; j < 4; j++) acc[i][j] = 0.f;

    __syncthreads();

    for (int st = 0; st < 32; st++) {
        for (int e = tid; e < 64 * 32; e += 256) {
            int c = e >> 5, s = e & 31;
            Ks[c][s] = kp[(size_t)c * T + st * 32 + s];
            Vs[c][s] = vp[(size_t)c * T + st * 32 + s];
        }
        __syncthreads();

        {
            float sc[4][2];
#pragma unroll
            for (int i = 0; i < 4; i++) { sc[i][0] = 0.f; sc[i][1] = 0.f; }
#pragma unroll
            for (int c = 0; c < 64; c++) {
                float4 qv = *(const float4*)&Qs[c][ty * 4];
                float k0 = Ks[c][tx * 2];
                float k1 = Ks[c][tx * 2 + 1];
                sc[0][0] = fmaf(qv.x, k0, sc[0][0]);
                sc[0][1] = fmaf(qv.x, k1, sc[0][1]);
                sc[1][0] = fmaf(qv.y, k0, sc[1][0]);
                sc[1][1] = fmaf(qv.y, k1, sc[1][1]);
                sc[2][0] = fmaf(qv.z, k0, sc[2][0]);
                sc[2][1] = fmaf(qv.z, k1, sc[2][1]);
                sc[3][0] = fmaf(qv.w, k0, sc[3][0]);
                sc[3][1] = fmaf(qv.w, k1, sc[3][1]);
            }
#pragma unroll
            for (int i = 0; i < 4; i++) {
                Sm[ty * 4 + i][tx * 2 + 0] = sc[i][0] * 0.125f;
                Sm[ty * 4 + i][tx * 2 + 1] = sc[i][1] * 0.125f;
            }
        }
        __syncthreads();

        // online softmax: 4 threads/row, xor-shuffle all-reduce in 4-lane group
        {
            const int s0 = ssub * 8;
            float mx = m_r;
#pragma unroll
            for (int s = 0; s < 8; s++) mx = fmaxf(mx, Sm[srow][s0 + s]);
            mx = fmaxf(mx, __shfl_xor_sync(0xffffffffu, mx, 1));
            mx = fmaxf(mx, __shfl_xor_sync(0xffffffffu, mx, 2));
            float fac = __expf(m_r - mx);
            float sum = 0.f;
#pragma unroll
            for (int s = 0; s < 8; s++) {
                float p = __expf(Sm[srow][s0 + s] - mx);
                Sm[srow][s0 + s] = p;
                sum += p;
            }
            sum += __shfl_xor_sync(0xffffffffu, sum, 1);
            sum += __shfl_xor_sync(0xffffffffu, sum, 2);
            l_r = l_r * fac + sum;
            m_r = mx;
            if (ssub == 0) lsc[srow] = fac;
        }
        __syncthreads();

        {
            float f[4];
#pragma unroll
            for (int i = 0; i < 4; i++) f[i] = lsc[ty * 4 + i];
#pragma unroll
            for (int i = 0; i < 4; i++)
#pragma unroll
                for (int j = 0; j < 4; j++) acc[i][j] *= f[i];
#pragma unroll 4
            for (int s = 0; s < 32; s++) {
                float p[4], v[4];
#pragma unroll
                for (int i = 0; i < 4; i++) p[i] = Sm[ty * 4 + i][s];
#pragma unroll
                for (int j = 0; j < 4; j++) v[j] = Vs[tx * 4 + j][s];
#pragma unroll
                for (int i = 0; i < 4; i++)
#pragma unroll
                    for (int j = 0; j < 4; j++)
                        acc[i][j] = fmaf(p[i], v[j], acc[i][j]);
            }
        }
        __syncthreads();
    }

    if (ssub == 0) linv[srow] = 1.0f / l_r;
    __syncthreads();

#pragma unroll
    for (int j = 0; j < 4; j++) {
        const size_t rowbase = ((size_t)bb * CH + h * 64 + tx * 4 + j) * T
                               + qt * 64 + ty * 4;
#pragma unroll
        for (int i = 0; i < 4; i++) {
            aout[rowbase + i] = acc[i][j] * linv[ty * 4 + i];
        }
    }
}

// ---------------------------------------------------------------------------
extern "C" void kernel_launch(void* const* d_in, const int* in_sizes, int n_in,
                              void* d_out, int out_size)
{
    const float* x      = (const float*)d_in[0];
    const float* norm_w = (const float*)d_in[1];
    const float* norm_b = (const float*)d_in[2];
    const float* qkv_w  = (const float*)d_in[3];
    const float* qkv_b  = (const float*)d_in[4];
    const float* proj_w = (const float*)d_in[5];
    const float* proj_b = (const float*)d_in[6];
    float* out = (float*)d_out;

    float* xn;   cudaGetSymbolAddress((void**)&xn,   g_xn);
    float* qkv;  cudaGetSymbolAddress((void**)&qkv,  g_qkv);
    float* attn; cudaGetSymbolAddress((void**)&attn, g_attn);

    // 1. GroupNorm
    groupnorm_kernel<<<BATCH * GROUPS, 256>>>(x, norm_w, norm_b, xn);

    // 2. QKV GEMM (tf32 tensor cores): (1536 x 512) x (512 x 1024) per batch
    gemm_tc_kernel<CH><<<dim3(T / 128, (3 * CH) / 128, BATCH), 256>>>(
        qkv_w, xn, qkv_b, nullptr, qkv, 3 * CH, T);

    // 3. Fused attention
    attn_kernel<<<dim3(BATCH * HEADS, T / 64), 256>>>(qkv, attn);

    // 4. Proj GEMM (tf32) + bias + residual
    gemm_tc_kernel<CH><<<dim3(T / 128, CH / 128, BATCH), 256>>>(
        proj_w, attn, proj_b, x, out, CH, T);
}